// round 2
// baseline (speedup 1.0000x reference)
#include <cuda_runtime.h>
#include <cuda_bf16.h>

// WindowAttention (Swin-style) fully fused, one CTA per window.
// B_=16384 windows, N=49 tokens, DIM=128, HEADS=4, hd=32, NW=256 mask groups.
//
// Per-CTA pipeline (all in dynamic SMEM, ~165 KB):
//   1. load x[b]            -> xs   [49 x 128]  (row stride 132 for bank safety)
//   2. qkv = x @ W_qkv^T+b  -> qs/ks/vs (q pre-scaled), W smem-tiled 64 rows
//   3. scores = q@k^T + rpb_bias + mask -> at [4][49][50]
//   4. softmax rows (fp32, __expf)
//   5. o = attn @ v         -> reuse xs buffer
//   6. out = o @ W_proj^T+b -> global (W smem-tiled)

#define NTOK 49
#define CDIM 128
#define NHEAD 4
#define NWIN 256
#define RS4 33              // row stride in float4 (132 floats) for padded tiles

#define OFF_XS 0
#define OFF_QS 6468
#define OFF_KS 12936
#define OFF_VS 19404
#define OFF_S  25872
#define SMEM_FLOATS 41150   // 25872 + 15278
// S sub-layout: at [0,9800)  mk [9800,12201)  rpi(int) [12201,14602)  rpb [14602,15278)
// wt (weight tile, 64*33 f4 = 8448 floats) aliases [0,8448) of S.

__global__ __launch_bounds__(512, 1)
void winattn_kernel(const float* __restrict__ x,
                    const float* __restrict__ mask,
                    const float* __restrict__ qkv_w,
                    const float* __restrict__ qkv_b,
                    const float* __restrict__ proj_w,
                    const float* __restrict__ proj_b,
                    const float* __restrict__ rpb,
                    const int*   __restrict__ rpi,
                    float* __restrict__ out)
{
    extern __shared__ float sm[];
    float4* sm4 = reinterpret_cast<float4*>(sm);

    const int b   = blockIdx.x;
    const int tid = threadIdx.x;

    float4* xs4 = sm4 + OFF_XS / 4;
    float4* qs4 = sm4 + OFF_QS / 4;
    float4* ks4 = sm4 + OFF_KS / 4;
    float4* vs4 = sm4 + OFF_VS / 4;
    float4* wt4 = sm4 + OFF_S  / 4;

    float* qs = sm + OFF_QS;
    float* ks = sm + OFF_KS;
    float* vs = sm + OFF_VS;
    float* at = sm + OFF_S;
    float* mk = sm + OFF_S + 9800;
    int*   rp = reinterpret_cast<int*>(sm + OFF_S + 12201);
    float* rb = sm + OFF_S + 14602;

    const float SCALE = 0.17677669529663687f;   // 32^-0.5

    // ---- 1. load x[b] into xs (1568 float4) ----
    const float4* xg = reinterpret_cast<const float4*>(x + (size_t)b * (NTOK * CDIM));
    for (int i = tid; i < NTOK * 32; i += 512) {
        int r = i >> 5, c = i & 31;
        xs4[r * RS4 + c] = xg[i];
    }
    __syncthreads();

    const int tn   = tid >> 5;   // 0..15, warp-uniform
    const int lane = tid & 31;
    const int n0   = tn * 4;

    // ---- 2. QKV projection, 6 weight tiles of 64 rows ----
    const float4* qw4 = reinterpret_cast<const float4*>(qkv_w);
    for (int t0 = 0; t0 < 384; t0 += 64) {
        for (int i = tid; i < 64 * 32; i += 512) {
            int r = i >> 5, c = i & 31;
            wt4[r * RS4 + c] = qw4[(t0 + r) * 32 + c];
        }
        __syncthreads();

        float acc[4][2];
        #pragma unroll
        for (int a = 0; a < 4; a++) { acc[a][0] = 0.f; acc[a][1] = 0.f; }

        int nr0 = (n0     < 48) ? n0     : 48;
        int nr1 = (n0 + 1 < 48) ? n0 + 1 : 48;
        int nr2 = (n0 + 2 < 48) ? n0 + 2 : 48;
        int nr3 = (n0 + 3 < 48) ? n0 + 3 : 48;

        #pragma unroll 4
        for (int c4 = 0; c4 < 32; c4++) {
            float4 a0 = xs4[nr0 * RS4 + c4];
            float4 a1 = xs4[nr1 * RS4 + c4];
            float4 a2 = xs4[nr2 * RS4 + c4];
            float4 a3 = xs4[nr3 * RS4 + c4];
            float4 b0 = wt4[lane * RS4 + c4];
            float4 b1 = wt4[(lane + 32) * RS4 + c4];
            acc[0][0] += a0.x*b0.x + a0.y*b0.y + a0.z*b0.z + a0.w*b0.w;
            acc[1][0] += a1.x*b0.x + a1.y*b0.y + a1.z*b0.z + a1.w*b0.w;
            acc[2][0] += a2.x*b0.x + a2.y*b0.y + a2.z*b0.z + a2.w*b0.w;
            acc[3][0] += a3.x*b0.x + a3.y*b0.y + a3.z*b0.z + a3.w*b0.w;
            acc[0][1] += a0.x*b1.x + a0.y*b1.y + a0.z*b1.z + a0.w*b1.w;
            acc[1][1] += a1.x*b1.x + a1.y*b1.y + a1.z*b1.z + a1.w*b1.w;
            acc[2][1] += a2.x*b1.x + a2.y*b1.y + a2.z*b1.z + a2.w*b1.w;
            acc[3][1] += a3.x*b1.x + a3.y*b1.y + a3.z*b1.z + a3.w*b1.w;
        }

        const int which = t0 >> 7;                // 0=q, 1=k, 2=v (uniform per tile)
        const int dbase = t0 & 127;
        float* dst = (which == 0) ? qs : ((which == 1) ? ks : vs);
        const float mul = (which == 0) ? SCALE : 1.0f;

        #pragma unroll
        for (int rr = 0; rr < 2; rr++) {
            int r  = lane + 32 * rr;
            int d3 = t0 + r;
            int d  = dbase + r;
            float bias = qkv_b[d3];
            #pragma unroll
            for (int nn = 0; nn < 4; nn++) {
                int n = n0 + nn;
                if (n < NTOK) dst[n * 132 + d] = (acc[nn][rr] + bias) * mul;
            }
        }
        __syncthreads();
    }

    // ---- load mask row-group, rpi, rpb table ----
    {
        const float* mg = mask + (size_t)(b & (NWIN - 1)) * (NTOK * NTOK);
        for (int i = tid; i < NTOK * NTOK; i += 512) { mk[i] = mg[i]; rp[i] = rpi[i]; }
        for (int i = tid; i < 169 * NHEAD; i += 512) rb[i] = rpb[i];
    }
    __syncthreads();

    // ---- 3. scores: 200 units = (h, i-pair, j-half) ----
    if (tid < 200) {
        int pair = tid & 1;
        int t2   = tid >> 1;         // 0..99
        int h    = t2 & 3;
        int i2   = t2 >> 2;          // 0..24
        int i0   = i2 * 2;
        int i1   = (i0 + 1 < NTOK) ? i0 + 1 : i0;

        float4 q0[8], q1[8];
        #pragma unroll
        for (int c4 = 0; c4 < 8; c4++) {
            q0[c4] = qs4[i0 * RS4 + h * 8 + c4];
            q1[c4] = qs4[i1 * RS4 + h * 8 + c4];
        }
        int j0 = pair * 25;
        int jn = pair ? 24 : 25;
        for (int jj = 0; jj < jn; jj++) {
            int j = j0 + jj;
            float a0 = 0.f, a1 = 0.f;
            #pragma unroll
            for (int c4 = 0; c4 < 8; c4++) {
                float4 kv = ks4[j * RS4 + h * 8 + c4];
                a0 += q0[c4].x*kv.x + q0[c4].y*kv.y + q0[c4].z*kv.z + q0[c4].w*kv.w;
                a1 += q1[c4].x*kv.x + q1[c4].y*kv.y + q1[c4].z*kv.z + q1[c4].w*kv.w;
            }
            float bias0 = rb[rp[i0 * NTOK + j] * NHEAD + h] + mk[i0 * NTOK + j];
            float bias1 = rb[rp[i1 * NTOK + j] * NHEAD + h] + mk[i1 * NTOK + j];
            at[(h * NTOK + i0) * 50 + j] = a0 + bias0;
            at[(h * NTOK + i1) * 50 + j] = a1 + bias1;
        }
    }
    __syncthreads();

    // ---- 4. softmax: one thread per (h,i) row ----
    if (tid < NHEAD * NTOK) {
        int h = tid & 3;
        int i = tid >> 2;
        float* row = at + (h * NTOK + i) * 50;
        float m = row[0];
        for (int j = 1; j < NTOK; j++) m = fmaxf(m, row[j]);
        float s = 0.f;
        for (int j = 0; j < NTOK; j++) { float e = __expf(row[j] - m); row[j] = e; s += e; }
        float inv = 1.0f / s;
        for (int j = 0; j < NTOK; j++) row[j] *= inv;
    }
    __syncthreads();

    // ---- 5. o = attn @ v  (write into xs buffer) ----
    for (int u = tid; u < NTOK * 32; u += 512) {
        int i  = u >> 5;
        int r  = u & 31;
        int h  = r >> 3;
        int d4 = r & 7;
        const float* arow = at + (h * NTOK + i) * 50;
        float4 acc = make_float4(0.f, 0.f, 0.f, 0.f);
        for (int j = 0; j < NTOK; j++) {
            float a = arow[j];
            float4 vv = vs4[j * RS4 + h * 8 + d4];
            acc.x += a * vv.x; acc.y += a * vv.y; acc.z += a * vv.z; acc.w += a * vv.w;
        }
        xs4[i * RS4 + h * 8 + d4] = acc;
    }
    __syncthreads();

    // ---- 6. output projection, 2 weight tiles of 64 rows ----
    float* og = out + (size_t)b * (NTOK * CDIM);
    const float4* pw4 = reinterpret_cast<const float4*>(proj_w);
    for (int t0 = 0; t0 < 128; t0 += 64) {
        for (int i = tid; i < 64 * 32; i += 512) {
            int r = i >> 5, c = i & 31;
            wt4[r * RS4 + c] = pw4[(t0 + r) * 32 + c];
        }
        __syncthreads();

        float acc[4][2];
        #pragma unroll
        for (int a = 0; a < 4; a++) { acc[a][0] = 0.f; acc[a][1] = 0.f; }

        int nr0 = (n0     < 48) ? n0     : 48;
        int nr1 = (n0 + 1 < 48) ? n0 + 1 : 48;
        int nr2 = (n0 + 2 < 48) ? n0 + 2 : 48;
        int nr3 = (n0 + 3 < 48) ? n0 + 3 : 48;

        #pragma unroll 4
        for (int c4 = 0; c4 < 32; c4++) {
            float4 a0 = xs4[nr0 * RS4 + c4];
            float4 a1 = xs4[nr1 * RS4 + c4];
            float4 a2 = xs4[nr2 * RS4 + c4];
            float4 a3 = xs4[nr3 * RS4 + c4];
            float4 b0 = wt4[lane * RS4 + c4];
            float4 b1 = wt4[(lane + 32) * RS4 + c4];
            acc[0][0] += a0.x*b0.x + a0.y*b0.y + a0.z*b0.z + a0.w*b0.w;
            acc[1][0] += a1.x*b0.x + a1.y*b0.y + a1.z*b0.z + a1.w*b0.w;
            acc[2][0] += a2.x*b0.x + a2.y*b0.y + a2.z*b0.z + a2.w*b0.w;
            acc[3][0] += a3.x*b0.x + a3.y*b0.y + a3.z*b0.z + a3.w*b0.w;
            acc[0][1] += a0.x*b1.x + a0.y*b1.y + a0.z*b1.z + a0.w*b1.w;
            acc[1][1] += a1.x*b1.x + a1.y*b1.y + a1.z*b1.z + a1.w*b1.w;
            acc[2][1] += a2.x*b1.x + a2.y*b1.y + a2.z*b1.z + a2.w*b1.w;
            acc[3][1] += a3.x*b1.x + a3.y*b1.y + a3.z*b1.z + a3.w*b1.w;
        }

        #pragma unroll
        for (int rr = 0; rr < 2; rr++) {
            int d = t0 + lane + 32 * rr;
            float bias = proj_b[d];
            #pragma unroll
            for (int nn = 0; nn < 4; nn++) {
                int n = n0 + nn;
                if (n < NTOK) og[n * CDIM + d] = acc[nn][rr] + bias;
            }
        }
        __syncthreads();
    }
}

extern "C" void kernel_launch(void* const* d_in, const int* in_sizes, int n_in,
                              void* d_out, int out_size)
{
    const float* x      = (const float*)d_in[0];
    const float* mask   = (const float*)d_in[1];
    const float* qkv_w  = (const float*)d_in[2];
    const float* qkv_b  = (const float*)d_in[3];
    const float* proj_w = (const float*)d_in[4];
    const float* proj_b = (const float*)d_in[5];
    const float* rpb    = (const float*)d_in[6];
    const int*   rpi    = (const int*)d_in[7];
    float* out = (float*)d_out;

    const size_t smem_bytes = (size_t)SMEM_FLOATS * sizeof(float);  // 164,600 B
    cudaFuncSetAttribute(winattn_kernel,
                         cudaFuncAttributeMaxDynamicSharedMemorySize,
                         (int)smem_bytes);

    winattn_kernel<<<16384, 512, smem_bytes>>>(x, mask, qkv_w, qkv_b,
                                               proj_w, proj_b, rpb, rpi, out);
}

// round 3
// speedup vs baseline: 3.9052x; 3.9052x over previous
#include <cuda_runtime.h>
#include <cuda_bf16.h>

// WindowAttention fused, tensor-core (tf32 mma.sync) version.
// One CTA per window (16384 CTAs), 256 threads (8 warps).
// B_=16384, N=49 tokens, DIM=128, HEADS=4, hd=32, NW=256 mask groups.
//
// All GEMMs via mma.sync.aligned.m16n8k8.row.col.f32.tf32.tf32.f32.
// Operands pre-rounded to tf32 when written to smem; fp32 accumulate.
//
// SMEM (floats), row stride RS=132 (bank = 4g+t permutation => conflict-free frags):
//  XS  [64x132]  x (tf32), later O (tf32)        @ 0
//  QS  [64x132]  q*scale (tf32)                  @ 8448
//  KS  [56x132]  k (tf32)                        @ 16896
//  VS  [56x132]  v (tf32), pad rows 49..55 = 0   @ 24288
//  AT  [4][64][56] scores/probs  (aliases WT)    @ 31680   (WT: 64x132 weight tile)
//  MK  [2401] mask, RP [2401] rpi, RB [676] rpb  @ 46016 / 48417 / 50818
// total 51494 floats = 205,976 B

#define RS     132
#define XS_OFF 0
#define QS_OFF 8448
#define KS_OFF 16896
#define VS_OFF 24288
#define AT_OFF 31680
#define MK_OFF 46016
#define RP_OFF 48417
#define RB_OFF 50818
#define SMEM_FLOATS 51494
#define AT_HS  3584   // 64*56 per head
#define AT_RS  56

__device__ __forceinline__ unsigned f2tf_u(float f) {
    unsigned u; asm("cvt.rna.tf32.f32 %0, %1;" : "=r"(u) : "f"(f)); return u;
}
__device__ __forceinline__ float f2tf(float f) { return __uint_as_float(f2tf_u(f)); }
__device__ __forceinline__ float4 round4(float4 v) {
    return make_float4(f2tf(v.x), f2tf(v.y), f2tf(v.z), f2tf(v.w));
}
__device__ __forceinline__ void mma8(float4& c, unsigned a0, unsigned a1, unsigned a2, unsigned a3,
                                     unsigned b0, unsigned b1) {
    asm volatile(
        "mma.sync.aligned.m16n8k8.row.col.f32.tf32.tf32.f32 "
        "{%0,%1,%2,%3},{%4,%5,%6,%7},{%8,%9},{%0,%1,%2,%3};"
        : "+f"(c.x), "+f"(c.y), "+f"(c.z), "+f"(c.w)
        : "r"(a0), "r"(a1), "r"(a2), "r"(a3), "r"(b0), "r"(b1));
}

__global__ __launch_bounds__(256, 1)
void winattn_tc(const float* __restrict__ x,
                const float* __restrict__ mask,
                const float* __restrict__ qkv_w,
                const float* __restrict__ qkv_b,
                const float* __restrict__ proj_w,
                const float* __restrict__ proj_b,
                const float* __restrict__ rpb,
                const int*   __restrict__ rpi,
                float* __restrict__ out)
{
    extern __shared__ float sm[];
    float4* sm4 = reinterpret_cast<float4*>(sm);

    const int b   = blockIdx.x;
    const int tid = threadIdx.x;
    const int w   = tid >> 5;
    const int l   = tid & 31;
    const int g   = l >> 2;     // 0..7
    const int t   = l & 3;      // 0..3

    float*  xs  = sm + XS_OFF;
    float*  qs  = sm + QS_OFF;
    float*  ks  = sm + KS_OFF;
    float*  vs  = sm + VS_OFF;
    float*  att = sm + AT_OFF;
    float*  wt  = sm + AT_OFF;          // alias (disjoint liveness)
    float*  mk  = sm + MK_OFF;
    int*    rp  = reinterpret_cast<int*>(sm + RP_OFF);
    float*  rb  = sm + RB_OFF;
    float4* xs4 = sm4 + XS_OFF / 4;
    float4* wt4 = sm4 + AT_OFF / 4;

    const float SCALE = 0.17677669529663687f;   // 32^-0.5

    // ---- init loads: x (rounded), mask/rpi/rpb, zero V/K pad rows, weight tile 0 ----
    {
        const float4* xg = reinterpret_cast<const float4*>(x + (size_t)b * (49 * 128));
        #pragma unroll
        for (int it = 0; it < 7; it++) {
            int idx = tid + it * 256;
            if (idx < 49 * 32) {
                int r = idx >> 5, c = idx & 31;
                xs4[r * 33 + c] = round4(xg[idx]);
            }
        }
        const float* mg = mask + (size_t)(b & 255) * (49 * 49);
        #pragma unroll
        for (int it = 0; it < 10; it++) {
            int idx = tid + it * 256;
            if (idx < 2401) { mk[idx] = mg[idx]; rp[idx] = rpi[idx]; }
        }
        #pragma unroll
        for (int it = 0; it < 3; it++) {
            int idx = tid + it * 256;
            if (idx < 676) rb[idx] = rpb[idx];
        }
        // zero K/V pad rows 49..55 (V mandatory: padded-k contraction in PV)
        for (int idx = tid; idx < 7 * RS; idx += 256) {
            ks[49 * RS + idx] = 0.f;
            vs[49 * RS + idx] = 0.f;
        }
    }

    const float4* qw4 = reinterpret_cast<const float4*>(qkv_w);
    const float4* pw4 = reinterpret_cast<const float4*>(proj_w);

    float4 pre[8];
    #pragma unroll
    for (int it = 0; it < 8; it++) pre[it] = qw4[tid + it * 256];     // tile 0
    #pragma unroll
    for (int it = 0; it < 8; it++) {
        int idx = tid + it * 256;
        wt4[(idx >> 5) * 33 + (idx & 31)] = round4(pre[it]);
    }
    __syncthreads();

    // ================= Phase A: QKV projection (6 weight tiles of 64 dims) =====
    {
        const int mt = w & 3, nh = w >> 2;
        const int r0 = mt * 16 + g, r1 = r0 + 8;

        for (int wi = 0; wi < 6; wi++) {
            if (wi < 5) {
                #pragma unroll
                for (int it = 0; it < 8; it++)
                    pre[it] = qw4[(wi + 1) * 2048 + tid + it * 256];
            }
            float4 acc[4];
            #pragma unroll
            for (int q4 = 0; q4 < 4; q4++) acc[q4] = make_float4(0.f, 0.f, 0.f, 0.f);

            #pragma unroll 4
            for (int kss = 0; kss < 16; kss++) {
                int k0 = kss * 8;
                unsigned a0 = __float_as_uint(xs[r0 * RS + k0 + t]);
                unsigned a1 = __float_as_uint(xs[r1 * RS + k0 + t]);
                unsigned a2 = __float_as_uint(xs[r0 * RS + k0 + t + 4]);
                unsigned a3 = __float_as_uint(xs[r1 * RS + k0 + t + 4]);
                #pragma unroll
                for (int n4 = 0; n4 < 4; n4++) {
                    int nb = (nh * 4 + n4) * 8;
                    unsigned b0 = __float_as_uint(wt[(nb + g) * RS + k0 + t]);
                    unsigned b1 = __float_as_uint(wt[(nb + g) * RS + k0 + t + 4]);
                    mma8(acc[n4], a0, a1, a2, a3, b0, b1);
                }
            }
            // epilogue
            const int which = wi >> 1;                 // 0=q 1=k 2=v
            float* dst = (which == 0) ? qs : ((which == 1) ? ks : vs);
            const float mul = (which == 0) ? SCALE : 1.0f;
            #pragma unroll
            for (int n4 = 0; n4 < 4; n4++) {
                int d3 = wi * 64 + (nh * 4 + n4) * 8 + 2 * t;
                int dc = (wi & 1) * 64 + (nh * 4 + n4) * 8 + 2 * t;
                float bx = qkv_b[d3], by = qkv_b[d3 + 1];
                if (r0 < 49) {
                    dst[r0 * RS + dc]     = f2tf((acc[n4].x + bx) * mul);
                    dst[r0 * RS + dc + 1] = f2tf((acc[n4].y + by) * mul);
                }
                if (r1 < 49) {
                    dst[r1 * RS + dc]     = f2tf((acc[n4].z + bx) * mul);
                    dst[r1 * RS + dc + 1] = f2tf((acc[n4].w + by) * mul);
                }
            }
            __syncthreads();
            if (wi < 5) {
                #pragma unroll
                for (int it = 0; it < 8; it++) {
                    int idx = tid + it * 256;
                    wt4[(idx >> 5) * 33 + (idx & 31)] = round4(pre[it]);
                }
                __syncthreads();
            }
        }
    }

    // ================= Phase B: scores = q@k^T + bias + mask ====================
    {
        const int h = w & 3, mg = w >> 2;
        float4 acc[2][7];
        #pragma unroll
        for (int mi = 0; mi < 2; mi++)
            #pragma unroll
            for (int nt = 0; nt < 7; nt++) acc[mi][nt] = make_float4(0.f, 0.f, 0.f, 0.f);

        #pragma unroll
        for (int kss = 0; kss < 4; kss++) {
            int k0 = h * 32 + kss * 8;
            unsigned a[2][4];
            #pragma unroll
            for (int mi = 0; mi < 2; mi++) {
                int r0 = (mg * 2 + mi) * 16 + g;
                a[mi][0] = __float_as_uint(qs[r0 * RS + k0 + t]);
                a[mi][1] = __float_as_uint(qs[(r0 + 8) * RS + k0 + t]);
                a[mi][2] = __float_as_uint(qs[r0 * RS + k0 + t + 4]);
                a[mi][3] = __float_as_uint(qs[(r0 + 8) * RS + k0 + t + 4]);
            }
            #pragma unroll
            for (int nt = 0; nt < 7; nt++) {
                unsigned b0 = __float_as_uint(ks[(nt * 8 + g) * RS + k0 + t]);
                unsigned b1 = __float_as_uint(ks[(nt * 8 + g) * RS + k0 + t + 4]);
                mma8(acc[0][nt], a[0][0], a[0][1], a[0][2], a[0][3], b0, b1);
                mma8(acc[1][nt], a[1][0], a[1][1], a[1][2], a[1][3], b0, b1);
            }
        }
        // epilogue: + rpb bias + mask; pad cols -> -1e30
        #pragma unroll
        for (int mi = 0; mi < 2; mi++) {
            int r0 = (mg * 2 + mi) * 16 + g;
            #pragma unroll
            for (int nt = 0; nt < 7; nt++) {
                int j0 = nt * 8 + 2 * t;
                float* base = att + h * AT_HS;
                #pragma unroll
                for (int e = 0; e < 4; e++) {
                    int i = (e & 2) ? r0 + 8 : r0;
                    int j = j0 + (e & 1);
                    float v = (e == 0) ? acc[mi][nt].x : (e == 1) ? acc[mi][nt].y
                            : (e == 2) ? acc[mi][nt].z : acc[mi][nt].w;
                    if (i < 49) {
                        if (j < 49)
                            base[i * AT_RS + j] = v + rb[rp[i * 49 + j] * 4 + h] + mk[i * 49 + j];
                        else
                            base[i * AT_RS + j] = -1e30f;
                    }
                }
            }
        }
    }
    __syncthreads();

    // ================= softmax (one thread per (h,i) row), round probs to tf32 ==
    if (tid < 196) {
        int h = tid / 49, i = tid - h * 49;
        float* row = att + h * AT_HS + i * AT_RS;
        float m = row[0];
        #pragma unroll 7
        for (int j = 1; j < 49; j++) m = fmaxf(m, row[j]);
        float s = 0.f;
        #pragma unroll 8
        for (int j = 0; j < 56; j++) { float e = __expf(row[j] - m); row[j] = e; s += e; }
        float inv = 1.0f / s;
        #pragma unroll 8
        for (int j = 0; j < 56; j++) row[j] = f2tf(row[j] * inv);
    }
    __syncthreads();

    // ================= Phase C: O = P @ V  (write tf32 O into XS) ==============
    {
        const int h = w & 3, mg = w >> 2;
        float4 acc[2][4];
        #pragma unroll
        for (int mi = 0; mi < 2; mi++)
            #pragma unroll
            for (int nd = 0; nd < 4; nd++) acc[mi][nd] = make_float4(0.f, 0.f, 0.f, 0.f);

        #pragma unroll
        for (int kss = 0; kss < 7; kss++) {
            int k0 = kss * 8;
            unsigned a[2][4];
            #pragma unroll
            for (int mi = 0; mi < 2; mi++) {
                int r0 = (mg * 2 + mi) * 16 + g;
                const float* base = att + h * AT_HS;
                a[mi][0] = __float_as_uint(base[r0 * AT_RS + k0 + t]);
                a[mi][1] = __float_as_uint(base[(r0 + 8) * AT_RS + k0 + t]);
                a[mi][2] = __float_as_uint(base[r0 * AT_RS + k0 + t + 4]);
                a[mi][3] = __float_as_uint(base[(r0 + 8) * AT_RS + k0 + t + 4]);
            }
            #pragma unroll
            for (int nd = 0; nd < 4; nd++) {
                unsigned b0 = __float_as_uint(vs[(k0 + t) * RS + h * 32 + nd * 8 + g]);
                unsigned b1 = __float_as_uint(vs[(k0 + t + 4) * RS + h * 32 + nd * 8 + g]);
                mma8(acc[0][nd], a[0][0], a[0][1], a[0][2], a[0][3], b0, b1);
                mma8(acc[1][nd], a[1][0], a[1][1], a[1][2], a[1][3], b0, b1);
            }
        }
        #pragma unroll
        for (int mi = 0; mi < 2; mi++) {
            int r0 = (mg * 2 + mi) * 16 + g, r1 = r0 + 8;
            #pragma unroll
            for (int nd = 0; nd < 4; nd++) {
                int c0 = h * 32 + nd * 8 + 2 * t;
                if (r0 < 49) {
                    xs[r0 * RS + c0]     = f2tf(acc[mi][nd].x);
                    xs[r0 * RS + c0 + 1] = f2tf(acc[mi][nd].y);
                }
                if (r1 < 49) {
                    xs[r1 * RS + c0]     = f2tf(acc[mi][nd].z);
                    xs[r1 * RS + c0 + 1] = f2tf(acc[mi][nd].w);
                }
            }
        }
    }
    __syncthreads();   // O in XS complete; AT region dead -> reuse as WT

    // ================= Phase D: out = O @ Wp^T + b (2 weight tiles) =============
    {
        #pragma unroll
        for (int it = 0; it < 8; it++) pre[it] = pw4[tid + it * 256];
        #pragma unroll
        for (int it = 0; it < 8; it++) {
            int idx = tid + it * 256;
            wt4[(idx >> 5) * 33 + (idx & 31)] = round4(pre[it]);
        }
        __syncthreads();

        const int mt = w & 3, nh = w >> 2;
        const int r0 = mt * 16 + g, r1 = r0 + 8;
        float* og = out + (size_t)b * (49 * 128);

        for (int wi = 0; wi < 2; wi++) {
            if (wi == 0) {
                #pragma unroll
                for (int it = 0; it < 8; it++) pre[it] = pw4[2048 + tid + it * 256];
            }
            float4 acc[4];
            #pragma unroll
            for (int q4 = 0; q4 < 4; q4++) acc[q4] = make_float4(0.f, 0.f, 0.f, 0.f);

            #pragma unroll 4
            for (int kss = 0; kss < 16; kss++) {
                int k0 = kss * 8;
                unsigned a0 = __float_as_uint(xs[r0 * RS + k0 + t]);
                unsigned a1 = __float_as_uint(xs[r1 * RS + k0 + t]);
                unsigned a2 = __float_as_uint(xs[r0 * RS + k0 + t + 4]);
                unsigned a3 = __float_as_uint(xs[r1 * RS + k0 + t + 4]);
                #pragma unroll
                for (int n4 = 0; n4 < 4; n4++) {
                    int nb = (nh * 4 + n4) * 8;
                    unsigned b0 = __float_as_uint(wt[(nb + g) * RS + k0 + t]);
                    unsigned b1 = __float_as_uint(wt[(nb + g) * RS + k0 + t + 4]);
                    mma8(acc[n4], a0, a1, a2, a3, b0, b1);
                }
            }
            #pragma unroll
            for (int n4 = 0; n4 < 4; n4++) {
                int d = wi * 64 + (nh * 4 + n4) * 8 + 2 * t;
                float bx = proj_b[d], by = proj_b[d + 1];
                if (r0 < 49) {
                    og[r0 * 128 + d]     = acc[n4].x + bx;
                    og[r0 * 128 + d + 1] = acc[n4].y + by;
                }
                if (r1 < 49) {
                    og[r1 * 128 + d]     = acc[n4].z + bx;
                    og[r1 * 128 + d + 1] = acc[n4].w + by;
                }
            }
            __syncthreads();
            if (wi == 0) {
                #pragma unroll
                for (int it = 0; it < 8; it++) {
                    int idx = tid + it * 256;
                    wt4[(idx >> 5) * 33 + (idx & 31)] = round4(pre[it]);
                }
                __syncthreads();
            }
        }
    }
}

extern "C" void kernel_launch(void* const* d_in, const int* in_sizes, int n_in,
                              void* d_out, int out_size)
{
    const float* x      = (const float*)d_in[0];
    const float* mask   = (const float*)d_in[1];
    const float* qkv_w  = (const float*)d_in[2];
    const float* qkv_b  = (const float*)d_in[3];
    const float* proj_w = (const float*)d_in[4];
    const float* proj_b = (const float*)d_in[5];
    const float* rpb    = (const float*)d_in[6];
    const int*   rpi    = (const int*)d_in[7];
    float* out = (float*)d_out;

    const size_t smem_bytes = (size_t)SMEM_FLOATS * sizeof(float);  // 205,976 B
    cudaFuncSetAttribute(winattn_tc,
                         cudaFuncAttributeMaxDynamicSharedMemorySize,
                         (int)smem_bytes);

    winattn_tc<<<16384, 256, smem_bytes>>>(x, mask, qkv_w, qkv_b,
                                           proj_w, proj_b, rpb, rpi, out);
}

// round 4
// speedup vs baseline: 4.5747x; 1.1714x over previous
#include <cuda_runtime.h>
#include <cuda_bf16.h>

// WindowAttention fused, tf32 mma.sync, 512 threads (16 warps), 1 CTA/window.
// B_=16384, N=49, DIM=128, HEADS=4, hd=32, NW=256.
//
// SMEM (floats), row stride RS=132 (bank = 4g+t => conflict-free fragments):
//  XS [64x132]  x (tf32), later O (tf32)           @ 0
//  QS [64x132]  q*scale (tf32)                     @ 8448
//  KS [56x132]  k (tf32)                           @ 16896
//  VS [56x132]  v (tf32), pad rows 49..55 = 0      @ 24288
//  AT [4][64][56] scores/probs  (aliases WT 128x132) @ 31680
//  MK [2401] mask @48576, RP [2401] rpi @50977, RB [676] rpb @53378
// total 54054 floats = 216,216 B

#define RS     132
#define XS_OFF 0
#define QS_OFF 8448
#define KS_OFF 16896
#define VS_OFF 24288
#define AT_OFF 31680
#define MK_OFF 48576
#define RP_OFF 50977
#define RB_OFF 53378
#define SMEM_FLOATS 54054
#define AT_HS  3584   // 64*56 per head
#define AT_RS  56

__device__ __forceinline__ unsigned f2tf_u(float f) {
    unsigned u; asm("cvt.rna.tf32.f32 %0, %1;" : "=r"(u) : "f"(f)); return u;
}
__device__ __forceinline__ float f2tf(float f) { return __uint_as_float(f2tf_u(f)); }
__device__ __forceinline__ float4 round4(float4 v) {
    return make_float4(f2tf(v.x), f2tf(v.y), f2tf(v.z), f2tf(v.w));
}
__device__ __forceinline__ void mma8(float4& c, unsigned a0, unsigned a1, unsigned a2, unsigned a3,
                                     unsigned b0, unsigned b1) {
    asm volatile(
        "mma.sync.aligned.m16n8k8.row.col.f32.tf32.tf32.f32 "
        "{%0,%1,%2,%3},{%4,%5,%6,%7},{%8,%9},{%0,%1,%2,%3};"
        : "+f"(c.x), "+f"(c.y), "+f"(c.z), "+f"(c.w)
        : "r"(a0), "r"(a1), "r"(a2), "r"(a3), "r"(b0), "r"(b1));
}

__global__ __launch_bounds__(512, 1)
void winattn_tc2(const float* __restrict__ x,
                 const float* __restrict__ mask,
                 const float* __restrict__ qkv_w,
                 const float* __restrict__ qkv_b,
                 const float* __restrict__ proj_w,
                 const float* __restrict__ proj_b,
                 const float* __restrict__ rpb,
                 const int*   __restrict__ rpi,
                 float* __restrict__ out)
{
    extern __shared__ float sm[];
    float4* sm4 = reinterpret_cast<float4*>(sm);

    const int b   = blockIdx.x;
    const int tid = threadIdx.x;
    const int w   = tid >> 5;
    const int l   = tid & 31;
    const int g   = l >> 2;     // 0..7
    const int t   = l & 3;      // 0..3

    float*  xs  = sm + XS_OFF;
    float*  qs  = sm + QS_OFF;
    float*  ks  = sm + KS_OFF;
    float*  vs  = sm + VS_OFF;
    float*  att = sm + AT_OFF;
    float*  wt  = sm + AT_OFF;          // alias (disjoint liveness)
    float*  mk  = sm + MK_OFF;
    int*    rp  = reinterpret_cast<int*>(sm + RP_OFF);
    float*  rb  = sm + RB_OFF;
    float4* xs4 = sm4 + XS_OFF / 4;
    float4* wt4 = sm4 + AT_OFF / 4;

    const float SCALE = 0.17677669529663687f;   // 32^-0.5

    // ---- init: x (tf32-rounded), mask/rpi/rpb, V pad rows zero ----
    {
        const float4* xg = reinterpret_cast<const float4*>(x + (size_t)b * (49 * 128));
        #pragma unroll
        for (int it = 0; it < 4; it++) {
            int idx = tid + it * 512;
            if (idx < 49 * 32) {
                int r = idx >> 5, c = idx & 31;
                xs4[r * 33 + c] = round4(xg[idx]);
            }
        }
        const float* mg = mask + (size_t)(b & 255) * (49 * 49);
        #pragma unroll
        for (int it = 0; it < 5; it++) {
            int idx = tid + it * 512;
            if (idx < 2401) { mk[idx] = mg[idx]; rp[idx] = rpi[idx]; }
        }
        #pragma unroll
        for (int it = 0; it < 2; it++) {
            int idx = tid + it * 512;
            if (idx < 676) rb[idx] = rpb[idx];
        }
        // zero V pad rows 49..55 (padded-k contraction in PV must be 0, not NaN)
        for (int idx = tid; idx < 7 * RS; idx += 512) vs[49 * RS + idx] = 0.f;
    }

    const float4* qw4 = reinterpret_cast<const float4*>(qkv_w);
    const float4* pw4 = reinterpret_cast<const float4*>(proj_w);

    // weight tile 0 (q): 128x32 float4 = 4096 f4, 8 per thread
    float4 pre[8];
    #pragma unroll
    for (int it = 0; it < 8; it++) pre[it] = qw4[tid + it * 512];
    #pragma unroll
    for (int it = 0; it < 8; it++) {
        int idx = tid + it * 512;
        wt4[(idx >> 5) * 33 + (idx & 31)] = round4(pre[it]);
    }
    __syncthreads();

    const int mt = w & 3, nh = w >> 2;        // 4 M-tiles x 4 N-slices
    const int r0 = mt * 16 + g, r1 = r0 + 8;

    // ================= Phase A: QKV projection, 3 tiles of 128 dims ============
    for (int wi = 0; wi < 3; wi++) {
        if (wi < 2) {
            #pragma unroll
            for (int it = 0; it < 8; it++)
                pre[it] = qw4[(wi + 1) * 4096 + tid + it * 512];
        }
        float4 acc[4];
        #pragma unroll
        for (int a = 0; a < 4; a++) acc[a] = make_float4(0.f, 0.f, 0.f, 0.f);

        #pragma unroll 4
        for (int kss = 0; kss < 16; kss++) {
            int k0 = kss * 8;
            unsigned a0 = __float_as_uint(xs[r0 * RS + k0 + t]);
            unsigned a1 = __float_as_uint(xs[r1 * RS + k0 + t]);
            unsigned a2 = __float_as_uint(xs[r0 * RS + k0 + t + 4]);
            unsigned a3 = __float_as_uint(xs[r1 * RS + k0 + t + 4]);
            #pragma unroll
            for (int n4 = 0; n4 < 4; n4++) {
                int row = nh * 32 + n4 * 8 + g;
                unsigned b0 = __float_as_uint(wt[row * RS + k0 + t]);
                unsigned b1 = __float_as_uint(wt[row * RS + k0 + t + 4]);
                mma8(acc[n4], a0, a1, a2, a3, b0, b1);
            }
        }
        float* dst = (wi == 0) ? qs : ((wi == 1) ? ks : vs);
        const float mul = (wi == 0) ? SCALE : 1.0f;
        #pragma unroll
        for (int n4 = 0; n4 < 4; n4++) {
            int d  = nh * 32 + n4 * 8 + 2 * t;
            int d3 = wi * 128 + d;
            float bx = qkv_b[d3], by = qkv_b[d3 + 1];
            if (r0 < 49) {
                dst[r0 * RS + d]     = f2tf((acc[n4].x + bx) * mul);
                dst[r0 * RS + d + 1] = f2tf((acc[n4].y + by) * mul);
            }
            if (r1 < 49) {
                dst[r1 * RS + d]     = f2tf((acc[n4].z + bx) * mul);
                dst[r1 * RS + d + 1] = f2tf((acc[n4].w + by) * mul);
            }
        }
        __syncthreads();
        if (wi < 2) {
            #pragma unroll
            for (int it = 0; it < 8; it++) {
                int idx = tid + it * 512;
                wt4[(idx >> 5) * 33 + (idx & 31)] = round4(pre[it]);
            }
            __syncthreads();
        }
    }

    // ================= Phase B: scores = q@k^T + bias + mask ====================
    {
        const int h = w & 3, mg2 = w >> 2;              // warp tile: 16 rows x 56 cols
        const int qr0 = mg2 * 16 + g, qr1 = qr0 + 8;
        float4 acc[7];
        #pragma unroll
        for (int nt = 0; nt < 7; nt++) acc[nt] = make_float4(0.f, 0.f, 0.f, 0.f);

        #pragma unroll
        for (int kss = 0; kss < 4; kss++) {
            int k0 = h * 32 + kss * 8;
            unsigned a0 = __float_as_uint(qs[qr0 * RS + k0 + t]);
            unsigned a1 = __float_as_uint(qs[qr1 * RS + k0 + t]);
            unsigned a2 = __float_as_uint(qs[qr0 * RS + k0 + t + 4]);
            unsigned a3 = __float_as_uint(qs[qr1 * RS + k0 + t + 4]);
            #pragma unroll
            for (int nt = 0; nt < 7; nt++) {
                unsigned b0 = __float_as_uint(ks[(nt * 8 + g) * RS + k0 + t]);
                unsigned b1 = __float_as_uint(ks[(nt * 8 + g) * RS + k0 + t + 4]);
                mma8(acc[nt], a0, a1, a2, a3, b0, b1);
            }
        }
        float* base = att + h * AT_HS;
        #pragma unroll
        for (int nt = 0; nt < 7; nt++) {
            int j0 = nt * 8 + 2 * t;
            #pragma unroll
            for (int e = 0; e < 4; e++) {
                int i = (e & 2) ? qr1 : qr0;
                int j = j0 + (e & 1);
                float v = (e == 0) ? acc[nt].x : (e == 1) ? acc[nt].y
                        : (e == 2) ? acc[nt].z : acc[nt].w;
                if (i < 49) {
                    base[i * AT_RS + j] = (j < 49)
                        ? v + rb[rp[i * 49 + j] * 4 + h] + mk[i * 49 + j]
                        : -1e30f;
                }
            }
        }
    }
    __syncthreads();

    // ================= softmax (one thread per (h,i) row), round probs to tf32 ==
    if (tid < 196) {
        int h = tid / 49, i = tid - h * 49;
        float* row = att + h * AT_HS + i * AT_RS;
        float m = row[0];
        #pragma unroll 7
        for (int j = 1; j < 49; j++) m = fmaxf(m, row[j]);
        float s = 0.f;
        #pragma unroll 8
        for (int j = 0; j < 56; j++) { float e = __expf(row[j] - m); row[j] = e; s += e; }
        float inv = 1.0f / s;
        #pragma unroll 8
        for (int j = 0; j < 56; j++) row[j] = f2tf(row[j] * inv);
    }
    __syncthreads();

    // ================= Phase C: O = P @ V  (tf32 O into XS) ====================
    {
        const int h = w & 3, mg2 = w >> 2;
        const int pr0 = mg2 * 16 + g, pr1 = pr0 + 8;
        const float* base = att + h * AT_HS;
        float4 acc[4];
        #pragma unroll
        for (int nd = 0; nd < 4; nd++) acc[nd] = make_float4(0.f, 0.f, 0.f, 0.f);

        #pragma unroll
        for (int kss = 0; kss < 7; kss++) {
            int k0 = kss * 8;
            unsigned a0 = __float_as_uint(base[pr0 * AT_RS + k0 + t]);
            unsigned a1 = __float_as_uint(base[pr1 * AT_RS + k0 + t]);
            unsigned a2 = __float_as_uint(base[pr0 * AT_RS + k0 + t + 4]);
            unsigned a3 = __float_as_uint(base[pr1 * AT_RS + k0 + t + 4]);
            #pragma unroll
            for (int nd = 0; nd < 4; nd++) {
                unsigned b0 = __float_as_uint(vs[(k0 + t) * RS + h * 32 + nd * 8 + g]);
                unsigned b1 = __float_as_uint(vs[(k0 + t + 4) * RS + h * 32 + nd * 8 + g]);
                mma8(acc[nd], a0, a1, a2, a3, b0, b1);
            }
        }
        #pragma unroll
        for (int nd = 0; nd < 4; nd++) {
            int c0 = h * 32 + nd * 8 + 2 * t;
            if (pr0 < 49) {
                xs[pr0 * RS + c0]     = f2tf(acc[nd].x);
                xs[pr0 * RS + c0 + 1] = f2tf(acc[nd].y);
            }
            if (pr1 < 49) {
                xs[pr1 * RS + c0]     = f2tf(acc[nd].z);
                xs[pr1 * RS + c0 + 1] = f2tf(acc[nd].w);
            }
        }
    }
    __syncthreads();   // O complete; AT dead -> reuse as WT

    // ================= Phase D: out = O @ Wp^T + b (single 128-dim tile) ========
    {
        #pragma unroll
        for (int it = 0; it < 8; it++) pre[it] = pw4[tid + it * 512];
        #pragma unroll
        for (int it = 0; it < 8; it++) {
            int idx = tid + it * 512;
            wt4[(idx >> 5) * 33 + (idx & 31)] = round4(pre[it]);
        }
        __syncthreads();

        float* og = out + (size_t)b * (49 * 128);
        float4 acc[4];
        #pragma unroll
        for (int a = 0; a < 4; a++) acc[a] = make_float4(0.f, 0.f, 0.f, 0.f);

        #pragma unroll 4
        for (int kss = 0; kss < 16; kss++) {
            int k0 = kss * 8;
            unsigned a0 = __float_as_uint(xs[r0 * RS + k0 + t]);
            unsigned a1 = __float_as_uint(xs[r1 * RS + k0 + t]);
            unsigned a2 = __float_as_uint(xs[r0 * RS + k0 + t + 4]);
            unsigned a3 = __float_as_uint(xs[r1 * RS + k0 + t + 4]);
            #pragma unroll
            for (int n4 = 0; n4 < 4; n4++) {
                int row = nh * 32 + n4 * 8 + g;
                unsigned b0 = __float_as_uint(wt[row * RS + k0 + t]);
                unsigned b1 = __float_as_uint(wt[row * RS + k0 + t + 4]);
                mma8(acc[n4], a0, a1, a2, a3, b0, b1);
            }
        }
        #pragma unroll
        for (int n4 = 0; n4 < 4; n4++) {
            int d = nh * 32 + n4 * 8 + 2 * t;
            float bx = proj_b[d], by = proj_b[d + 1];
            if (r0 < 49) {
                og[r0 * 128 + d]     = acc[n4].x + bx;
                og[r0 * 128 + d + 1] = acc[n4].y + by;
            }
            if (r1 < 49) {
                og[r1 * 128 + d]     = acc[n4].z + bx;
                og[r1 * 128 + d + 1] = acc[n4].w + by;
            }
        }
    }
}

extern "C" void kernel_launch(void* const* d_in, const int* in_sizes, int n_in,
                              void* d_out, int out_size)
{
    const float* x      = (const float*)d_in[0];
    const float* mask   = (const float*)d_in[1];
    const float* qkv_w  = (const float*)d_in[2];
    const float* qkv_b  = (const float*)d_in[3];
    const float* proj_w = (const float*)d_in[4];
    const float* proj_b = (const float*)d_in[5];
    const float* rpb    = (const float*)d_in[6];
    const int*   rpi    = (const int*)d_in[7];
    float* out = (float*)d_out;

    const size_t smem_bytes = (size_t)SMEM_FLOATS * sizeof(float);  // 216,216 B
    cudaFuncSetAttribute(winattn_tc2,
                         cudaFuncAttributeMaxDynamicSharedMemorySize,
                         (int)smem_bytes);

    winattn_tc2<<<16384, 512, smem_bytes>>>(x, mask, qkv_w, qkv_b,
                                            proj_w, proj_b, rpb, rpi, out);
}

// round 7
// speedup vs baseline: 6.3850x; 1.3957x over previous
#include <cuda_runtime.h>
#include <cuda_fp16.h>

// WindowAttention fused, fp16 mma.sync (m16n8k16, fp32 accumulate).
// One CTA per window (16384), 512 threads (16 warps).
// B_=16384, N=49, DIM=128, HEADS=4, hd=32, NW=256.
//
// SMEM byte layout (base = dynamic smem, 185,624 B total):
//  XS  half[64][136]   x, later O          @ 0       (17408 B)
//  QS  half[64][136]   q*scale             @ 17408   (17408 B)
//  KS  half[56][136]   k                   @ 34816   (15232 B)
//  VT  half[128][72]   V transposed, zeroed@ 50048   (18432 B)
//  ATH half[4][64][72] probs               @ 68480   (36864 B)
//  WT  half[128][136]  weight tile  ─┐     @ 105344  (34816 B)
//  AT32 float[4][64][57] scores     ─┴ alias @105344 (58368 B)
//  MK  float[2401]                        @ 163712
//  RP  int[2401]                          @ 173316
//  RB  float[676]                         @ 182920 .. 185624
// Strides: 136 halves = 68 words ≡ 4 (mod 32) and 72 halves = 36 words ≡ 4
// => fragment bank index = 4g+t : conflict-free.

#define RSH 136
#define VTS 72
#define SMEM_BYTES 185624

__device__ __forceinline__ unsigned ldu(const __half* p) {
    return *reinterpret_cast<const unsigned*>(p);
}
__device__ __forceinline__ void st2(__half* p, float a, float b) {
    *reinterpret_cast<__half2*>(p) = __floats2half2_rn(a, b);
}
__device__ __forceinline__ void mma16(float4& c, unsigned a0, unsigned a1, unsigned a2,
                                      unsigned a3, unsigned b0, unsigned b1) {
    asm volatile(
        "mma.sync.aligned.m16n8k16.row.col.f32.f16.f16.f32 "
        "{%0,%1,%2,%3},{%4,%5,%6,%7},{%8,%9},{%0,%1,%2,%3};"
        : "+f"(c.x), "+f"(c.y), "+f"(c.z), "+f"(c.w)
        : "r"(a0), "r"(a1), "r"(a2), "r"(a3), "r"(b0), "r"(b1));
}

__global__ __launch_bounds__(512, 1)
void winattn_h(const float* __restrict__ x,
               const float* __restrict__ mask,
               const float* __restrict__ qkv_w,
               const float* __restrict__ qkv_b,
               const float* __restrict__ proj_w,
               const float* __restrict__ proj_b,
               const float* __restrict__ rpb,
               const int*   __restrict__ rpi,
               float* __restrict__ out)
{
    extern __shared__ __align__(16) char smb[];
    __half* xs  = reinterpret_cast<__half*>(smb);
    __half* qs  = reinterpret_cast<__half*>(smb + 17408);
    __half* ks  = reinterpret_cast<__half*>(smb + 34816);
    __half* vt  = reinterpret_cast<__half*>(smb + 50048);
    __half* ath = reinterpret_cast<__half*>(smb + 68480);
    __half* wt  = reinterpret_cast<__half*>(smb + 105344);
    float* at32 = reinterpret_cast<float*>(smb + 105344);   // alias WT (disjoint liveness)
    float* mk   = reinterpret_cast<float*>(smb + 163712);
    int*   rp   = reinterpret_cast<int*>(smb + 173316);
    float* rb   = reinterpret_cast<float*>(smb + 182920);

    const int b   = blockIdx.x;
    const int tid = threadIdx.x;
    const int w   = tid >> 5;
    const int l   = tid & 31;
    const int g   = l >> 2;
    const int t   = l & 3;
    const int t2  = 2 * t;

    const float SCALE = 0.17677669529663687f;   // 32^-0.5

    // ---- init: x -> half, mask/rpi/rpb, zero VT ----
    {
        const float4* xg = reinterpret_cast<const float4*>(x + (size_t)b * (49 * 128));
        #pragma unroll
        for (int it = 0; it < 4; it++) {
            int idx = tid + it * 512;
            if (idx < 49 * 32) {
                int r = idx >> 5, c = idx & 31;
                float4 v = xg[idx];
                __half* p = xs + r * RSH + c * 4;
                *reinterpret_cast<__half2*>(p)     = __floats2half2_rn(v.x, v.y);
                *reinterpret_cast<__half2*>(p + 2) = __floats2half2_rn(v.z, v.w);
            }
        }
        const float* mg = mask + (size_t)(b & 255) * (49 * 49);
        #pragma unroll
        for (int it = 0; it < 5; it++) {
            int idx = tid + it * 512;
            if (idx < 2401) { mk[idx] = mg[idx]; rp[idx] = rpi[idx]; }
        }
        #pragma unroll
        for (int it = 0; it < 2; it++) {
            int idx = tid + it * 512;
            if (idx < 676) rb[idx] = rpb[idx];
        }
        int* vtw = reinterpret_cast<int*>(vt);      // zero all of VT (pad tokens must be 0)
        #pragma unroll
        for (int it = 0; it < 9; it++) {
            int idx = tid + it * 512;
            if (idx < 4608) vtw[idx] = 0;
        }
    }

    const float4* qw4 = reinterpret_cast<const float4*>(qkv_w);
    const float4* pw4 = reinterpret_cast<const float4*>(proj_w);

    float4 pre[8];
    #pragma unroll
    for (int it = 0; it < 8; it++) pre[it] = qw4[tid + it * 512];  // q-weight tile
    #pragma unroll
    for (int it = 0; it < 8; it++) {
        int idx = tid + it * 512;
        __half* p = wt + (idx >> 5) * RSH + (idx & 31) * 4;
        *reinterpret_cast<__half2*>(p)     = __floats2half2_rn(pre[it].x, pre[it].y);
        *reinterpret_cast<__half2*>(p + 2) = __floats2half2_rn(pre[it].z, pre[it].w);
    }
    __syncthreads();

    const int mt = w & 3, nh = w >> 2;
    const int r0 = mt * 16 + g, r1 = r0 + 8;
    const bool v0 = r0 < 49, v1 = r1 < 49;

    // ================ Phase A: QKV projection, 3 tiles of 128 out-dims ========
    for (int wi = 0; wi < 3; wi++) {
        if (wi < 2) {
            #pragma unroll
            for (int it = 0; it < 8; it++)
                pre[it] = qw4[(wi + 1) * 4096 + tid + it * 512];
        }
        float4 acc[4];
        #pragma unroll
        for (int a = 0; a < 4; a++) acc[a] = make_float4(0.f, 0.f, 0.f, 0.f);

        #pragma unroll
        for (int kss = 0; kss < 8; kss++) {
            int k0 = kss * 16;
            unsigned a0 = ldu(xs + r0 * RSH + k0 + t2);
            unsigned a1 = ldu(xs + r1 * RSH + k0 + t2);
            unsigned a2 = ldu(xs + r0 * RSH + k0 + 8 + t2);
            unsigned a3 = ldu(xs + r1 * RSH + k0 + 8 + t2);
            #pragma unroll
            for (int n4 = 0; n4 < 4; n4++) {
                const __half* wr = wt + (nh * 32 + n4 * 8 + g) * RSH + k0 + t2;
                mma16(acc[n4], a0, a1, a2, a3, ldu(wr), ldu(wr + 8));
            }
        }
        #pragma unroll
        for (int n4 = 0; n4 < 4; n4++) {
            int d  = nh * 32 + n4 * 8 + t2;
            int d3 = wi * 128 + d;
            float bx = qkv_b[d3], by = qkv_b[d3 + 1];
            if (wi == 0) {
                if (v0) st2(qs + r0 * RSH + d, (acc[n4].x + bx) * SCALE, (acc[n4].y + by) * SCALE);
                if (v1) st2(qs + r1 * RSH + d, (acc[n4].z + bx) * SCALE, (acc[n4].w + by) * SCALE);
            } else if (wi == 1) {
                if (v0) st2(ks + r0 * RSH + d, acc[n4].x + bx, acc[n4].y + by);
                if (v1) st2(ks + r1 * RSH + d, acc[n4].z + bx, acc[n4].w + by);
            } else {     // V: transposed into VT[dim][token]
                if (v0) {
                    vt[d * VTS + r0]       = __float2half_rn(acc[n4].x + bx);
                    vt[(d + 1) * VTS + r0] = __float2half_rn(acc[n4].y + by);
                }
                if (v1) {
                    vt[d * VTS + r1]       = __float2half_rn(acc[n4].z + bx);
                    vt[(d + 1) * VTS + r1] = __float2half_rn(acc[n4].w + by);
                }
            }
        }
        __syncthreads();
        if (wi < 2) {
            #pragma unroll
            for (int it = 0; it < 8; it++) {
                int idx = tid + it * 512;
                __half* p = wt + (idx >> 5) * RSH + (idx & 31) * 4;
                *reinterpret_cast<__half2*>(p)     = __floats2half2_rn(pre[it].x, pre[it].y);
                *reinterpret_cast<__half2*>(p + 2) = __floats2half2_rn(pre[it].z, pre[it].w);
            }
            __syncthreads();
        }
    }

    // ================ Phase B: scores = q@k^T + bias + mask (fp32) ============
    {
        const int h = w & 3, mq = w >> 2;
        const int qr0 = mq * 16 + g, qr1 = qr0 + 8;
        float4 acc[7];
        #pragma unroll
        for (int nt = 0; nt < 7; nt++) acc[nt] = make_float4(0.f, 0.f, 0.f, 0.f);

        #pragma unroll
        for (int kss = 0; kss < 2; kss++) {
            int k0 = h * 32 + kss * 16;
            unsigned a0 = ldu(qs + qr0 * RSH + k0 + t2);
            unsigned a1 = ldu(qs + qr1 * RSH + k0 + t2);
            unsigned a2 = ldu(qs + qr0 * RSH + k0 + 8 + t2);
            unsigned a3 = ldu(qs + qr1 * RSH + k0 + 8 + t2);
            #pragma unroll
            for (int nt = 0; nt < 7; nt++) {
                const __half* kr = ks + (nt * 8 + g) * RSH + k0 + t2;
                mma16(acc[nt], a0, a1, a2, a3, ldu(kr), ldu(kr + 8));
            }
        }
        #pragma unroll
        for (int nt = 0; nt < 7; nt++) {
            int j0 = nt * 8 + t2;
            if (qr0 < 49) {
                if (j0 < 49)
                    at32[(h * 64 + qr0) * 57 + j0] = acc[nt].x + rb[rp[qr0 * 49 + j0] * 4 + h] + mk[qr0 * 49 + j0];
                if (j0 + 1 < 49)
                    at32[(h * 64 + qr0) * 57 + j0 + 1] = acc[nt].y + rb[rp[qr0 * 49 + j0 + 1] * 4 + h] + mk[qr0 * 49 + j0 + 1];
            }
            if (qr1 < 49) {
                if (j0 < 49)
                    at32[(h * 64 + qr1) * 57 + j0] = acc[nt].z + rb[rp[qr1 * 49 + j0] * 4 + h] + mk[qr1 * 49 + j0];
                if (j0 + 1 < 49)
                    at32[(h * 64 + qr1) * 57 + j0 + 1] = acc[nt].w + rb[rp[qr1 * 49 + j0 + 1] * 4 + h] + mk[qr1 * 49 + j0 + 1];
            }
        }
    }
    __syncthreads();

    // ================ softmax: one thread per (h,i); probs -> half ============
    if (tid < 196) {
        int h = tid / 49, i = tid - h * 49;
        float* row = at32 + (h * 64 + i) * 57;
        __half* prow = ath + (h * 64 + i) * VTS;
        float m = row[0];
        #pragma unroll 7
        for (int j = 1; j < 49; j++) m = fmaxf(m, row[j]);
        float s = 0.f;
        #pragma unroll 7
        for (int j = 0; j < 49; j++) { float e = __expf(row[j] - m); row[j] = e; s += e; }
        float inv = 1.0f / s;
        #pragma unroll 8
        for (int j = 0; j < 64; j++)
            prow[j] = (j < 49) ? __float2half_rn(row[j] * inv) : __ushort_as_half(0);
    }
    __syncthreads();

    // prefetch proj_w tile while Phase C computes
    #pragma unroll
    for (int it = 0; it < 8; it++) pre[it] = pw4[tid + it * 512];

    // ================ Phase C: O = P @ V  (half O into XS) ====================
    {
        const int h = w & 3, mq = w >> 2;
        const int pr0 = mq * 16 + g, pr1 = pr0 + 8;
        const __half* pb = ath + h * 64 * VTS;
        float4 acc[4];
        #pragma unroll
        for (int nd = 0; nd < 4; nd++) acc[nd] = make_float4(0.f, 0.f, 0.f, 0.f);

        #pragma unroll
        for (int kss = 0; kss < 4; kss++) {
            int k0 = kss * 16;
            unsigned a0 = ldu(pb + pr0 * VTS + k0 + t2);
            unsigned a1 = ldu(pb + pr1 * VTS + k0 + t2);
            unsigned a2 = ldu(pb + pr0 * VTS + k0 + 8 + t2);
            unsigned a3 = ldu(pb + pr1 * VTS + k0 + 8 + t2);
            #pragma unroll
            for (int nd = 0; nd < 4; nd++) {
                const __half* vr = vt + (h * 32 + nd * 8 + g) * VTS + k0 + t2;
                mma16(acc[nd], a0, a1, a2, a3, ldu(vr), ldu(vr + 8));
            }
        }
        #pragma unroll
        for (int nd = 0; nd < 4; nd++) {
            int c0 = h * 32 + nd * 8 + t2;
            if (pr0 < 49) st2(xs + pr0 * RSH + c0, acc[nd].x, acc[nd].y);
            if (pr1 < 49) st2(xs + pr1 * RSH + c0, acc[nd].z, acc[nd].w);
        }
    }
    __syncthreads();   // O done; AT32/WT region dead -> store proj weights

    #pragma unroll
    for (int it = 0; it < 8; it++) {
        int idx = tid + it * 512;
        __half* p = wt + (idx >> 5) * RSH + (idx & 31) * 4;
        *reinterpret_cast<__half2*>(p)     = __floats2half2_rn(pre[it].x, pre[it].y);
        *reinterpret_cast<__half2*>(p + 2) = __floats2half2_rn(pre[it].z, pre[it].w);
    }
    __syncthreads();

    // ================ Phase D: out = O @ Wp^T + b =============================
    {
        float* og = out + (size_t)b * (49 * 128);
        float4 acc[4];
        #pragma unroll
        for (int a = 0; a < 4; a++) acc[a] = make_float4(0.f, 0.f, 0.f, 0.f);

        #pragma unroll
        for (int kss = 0; kss < 8; kss++) {
            int k0 = kss * 16;
            unsigned a0 = ldu(xs + r0 * RSH + k0 + t2);
            unsigned a1 = ldu(xs + r1 * RSH + k0 + t2);
            unsigned a2 = ldu(xs + r0 * RSH + k0 + 8 + t2);
            unsigned a3 = ldu(xs + r1 * RSH + k0 + 8 + t2);
            #pragma unroll
            for (int n4 = 0; n4 < 4; n4++) {
                const __half* wr = wt + (nh * 32 + n4 * 8 + g) * RSH + k0 + t2;
                mma16(acc[n4], a0, a1, a2, a3, ldu(wr), ldu(wr + 8));
            }
        }
        #pragma unroll
        for (int n4 = 0; n4 < 4; n4++) {
            int d = nh * 32 + n4 * 8 + t2;
            float bx = proj_b[d], by = proj_b[d + 1];
            if (v0) {
                og[r0 * 128 + d]     = acc[n4].x + bx;
                og[r0 * 128 + d + 1] = acc[n4].y + by;
            }
            if (v1) {
                og[r1 * 128 + d]     = acc[n4].z + bx;
                og[r1 * 128 + d + 1] = acc[n4].w + by;
            }
        }
    }
}

extern "C" void kernel_launch(void* const* d_in, const int* in_sizes, int n_in,
                              void* d_out, int out_size)
{
    const float* x      = (const float*)d_in[0];
    const float* mask   = (const float*)d_in[1];
    const float* qkv_w  = (const float*)d_in[2];
    const float* qkv_b  = (const float*)d_in[3];
    const float* proj_w = (const float*)d_in[4];
    const float* proj_b = (const float*)d_in[5];
    const float* rpb    = (const float*)d_in[6];
    const int*   rpi    = (const int*)d_in[7];
    float* out = (float*)d_out;

    cudaFuncSetAttribute(winattn_h,
                         cudaFuncAttributeMaxDynamicSharedMemorySize,
                         SMEM_BYTES);

    winattn_h<<<16384, 512, SMEM_BYTES>>>(x, mask, qkv_w, qkv_b,
                                          proj_w, proj_b, rpb, rpi, out);
}

// round 10
// speedup vs baseline: 10.3737x; 1.6247x over previous
#include <cuda_runtime.h>
#include <cuda_fp16.h>

// WindowAttention fused, fp16 mma.sync + ldmatrix + cp.async + register softmax.
// Precompute kernel: half weights + combined (rpb-gather + mask) bias table.
// Main: one CTA per window (16384), 512 threads (16 warps).
// B_=16384, N=49, DIM=128, HEADS=4, hd=32, NW=256.
//
// SMEM (bytes, all bases 128B-aligned):
//  XS  half[64][136]   x, later O            @ 0       (17408)
//  QS  half[64][136]   q*scale               @ 17408   (17408)
//  KS  half[56][136]   k (pad rows zeroed)   @ 34816   (15232)
//  VT  half[128][72]   V^T [dim][tok], zeroed@ 50048   (18432)
//  ATH half[4][64][72] probs, zeroed         @ 68480   (36864)
//  CB  half[4][49][56] combined bias         @ 105344  (21952)
//  WT0 half[128][136]  weight tile buf 0     @ 127360  (34816)
//  WT1 half[128][136]  weight tile buf 1     @ 162176  (34816)
// total 196992 B.
// Strides 136/72 halves (68/36 words == 4 mod 32) -> conflict-free fragments;
// 272B/144B rows = 17/9 x16B -> ldmatrix conflict-free.

#define XS_OFF   0
#define QS_OFF   17408
#define KS_OFF   34816
#define VT_OFF   50048
#define ATH_OFF  68480
#define CB_OFF   105344
#define WT0_OFF  127360
#define WT1_OFF  162176
#define SMEM_BYTES 196992
#define RSH 136
#define VTS 72
#define ATS 72
// KS pad rows (49..55) start: KS_OFF + 49*272 = 48144; contiguous with VT+ATH.
#define ZERO_OFF 48144
#define ZERO_U4  3575   // (1904 + 18432 + 36864) / 16

__device__ __half g_qkvw[384 * 128];
__device__ __half g_projw[128 * 128];
__device__ __half g_cbias[256 * 4 * 49 * 56];   // [wg][h][i][j-padded]

// ---------------- precompute: half weights + combined bias ------------------
__global__ void precompute_k(const float* __restrict__ mask,
                             const float* __restrict__ qkv_w,
                             const float* __restrict__ proj_w,
                             const float* __restrict__ rpb,
                             const int*   __restrict__ rpi)
{
    int blk = blockIdx.x, tid = threadIdx.x;
    if (blk < 256) {
        const float* mg = mask + (size_t)blk * 2401;
        __half* dst = g_cbias + (size_t)blk * 10976;
        for (int idx = tid; idx < 10976; idx += 256) {
            int h = idx / 2744, rem = idx - h * 2744;
            int i = rem / 56, j = rem - i * 56;
            float v = (j < 49) ? rpb[rpi[i * 49 + j] * 4 + h] + mg[i * 49 + j]
                               : -20000.0f;
            dst[idx] = __float2half_rn(v);
        }
    } else if (blk < 259) {
        int base = (blk - 256) * 16384;
        for (int idx = tid; idx < 16384; idx += 256)
            g_qkvw[base + idx] = __float2half_rn(qkv_w[base + idx]);
    } else {
        for (int idx = tid; idx < 16384; idx += 256)
            g_projw[idx] = __float2half_rn(proj_w[idx]);
    }
}

// ---------------- helpers ---------------------------------------------------
__device__ __forceinline__ void cpa16(unsigned dst, const void* src) {
    asm volatile("cp.async.cg.shared.global [%0], [%1], 16;" :: "r"(dst), "l"(src));
}
#define CPA_COMMIT() asm volatile("cp.async.commit_group;")
#define CPA_WAIT(n)  asm volatile("cp.async.wait_group %0;" :: "n"(n))

__device__ __forceinline__ void ldsm4(unsigned addr, unsigned& r0, unsigned& r1,
                                      unsigned& r2, unsigned& r3) {
    asm volatile("ldmatrix.sync.aligned.m8n8.x4.shared.b16 {%0,%1,%2,%3}, [%4];"
                 : "=r"(r0), "=r"(r1), "=r"(r2), "=r"(r3) : "r"(addr));
}
__device__ __forceinline__ void ldsm2(unsigned addr, unsigned& r0, unsigned& r1) {
    asm volatile("ldmatrix.sync.aligned.m8n8.x2.shared.b16 {%0,%1}, [%2];"
                 : "=r"(r0), "=r"(r1) : "r"(addr));
}
__device__ __forceinline__ void mma16(float4& c, unsigned a0, unsigned a1, unsigned a2,
                                      unsigned a3, unsigned b0, unsigned b1) {
    asm volatile(
        "mma.sync.aligned.m16n8k16.row.col.f32.f16.f16.f32 "
        "{%0,%1,%2,%3},{%4,%5,%6,%7},{%8,%9},{%0,%1,%2,%3};"
        : "+f"(c.x), "+f"(c.y), "+f"(c.z), "+f"(c.w)
        : "r"(a0), "r"(a1), "r"(a2), "r"(a3), "r"(b0), "r"(b1));
}
__device__ __forceinline__ void st2(__half* p, float a, float b) {
    *reinterpret_cast<__half2*>(p) = __floats2half2_rn(a, b);
}

// ---------------- main kernel ----------------------------------------------
__global__ __launch_bounds__(512, 1)
void winattn_h2(const float* __restrict__ x,
                const float* __restrict__ qkv_b,
                const float* __restrict__ proj_b,
                float* __restrict__ out)
{
    extern __shared__ __align__(16) char smb[];
    __half* xs  = reinterpret_cast<__half*>(smb + XS_OFF);
    __half* qs  = reinterpret_cast<__half*>(smb + QS_OFF);
    __half* ks  = reinterpret_cast<__half*>(smb + KS_OFF);
    __half* vt  = reinterpret_cast<__half*>(smb + VT_OFF);
    __half* ath = reinterpret_cast<__half*>(smb + ATH_OFF);
    const __half* cb = reinterpret_cast<const __half*>(smb + CB_OFF);

    const unsigned su = (unsigned)__cvta_generic_to_shared(smb);

    const int b   = blockIdx.x;
    const int tid = threadIdx.x;
    const int w   = tid >> 5;
    const int l   = tid & 31;
    const int g   = l >> 2;
    const int t   = l & 3;
    const int t2  = 2 * t;
    const int l15 = l & 15, lhi = (l >> 4) << 3, l7 = l & 7, l8 = l & 8;

    const float SCALE = 0.17677669529663687f;   // 32^-0.5

    // -- cp.async: weight tile 0 (G0 incl. CB), tile 1 (G1) --
    {
        const __half* wsrc = g_qkvw;
        unsigned wdst = su + WT0_OFF;
        #pragma unroll
        for (int it = 0; it < 4; it++) {
            int idx = tid + it * 512, r = idx >> 4, c = idx & 15;
            cpa16(wdst + r * 272 + c * 16, wsrc + r * 128 + c * 8);
        }
        const __half* cbsrc = g_cbias + (size_t)(b & 255) * 10976;
        #pragma unroll
        for (int it = 0; it < 3; it++) {
            int idx = tid + it * 512;
            if (idx < 1372) cpa16(su + CB_OFF + idx * 16, cbsrc + idx * 8);
        }
        CPA_COMMIT();                                   // G0
        wsrc = g_qkvw + 128 * 128;
        wdst = su + WT1_OFF;
        #pragma unroll
        for (int it = 0; it < 4; it++) {
            int idx = tid + it * 512, r = idx >> 4, c = idx & 15;
            cpa16(wdst + r * 272 + c * 16, wsrc + r * 128 + c * 8);
        }
        CPA_COMMIT();                                   // G1
    }

    // -- x -> XS (half); zero KS pad rows + VT + ATH (one contiguous region) --
    {
        const float4* xg = reinterpret_cast<const float4*>(x + (size_t)b * (49 * 128));
        #pragma unroll
        for (int it = 0; it < 4; it++) {
            int idx = tid + it * 512;
            if (idx < 49 * 32) {
                int r = idx >> 5, c = idx & 31;
                float4 v = xg[idx];
                __half* p = xs + r * RSH + c * 4;
                *reinterpret_cast<__half2*>(p)     = __floats2half2_rn(v.x, v.y);
                *reinterpret_cast<__half2*>(p + 2) = __floats2half2_rn(v.z, v.w);
            }
        }
        uint4 z = make_uint4(0, 0, 0, 0);
        uint4* zp = reinterpret_cast<uint4*>(smb + ZERO_OFF);
        #pragma unroll
        for (int it = 0; it < 7; it++) {
            int idx = tid + it * 512;
            if (idx < ZERO_U4) zp[idx] = z;
        }
    }

    const int mt = w & 3, nh = w >> 2;
    const int r0 = mt * 16 + g, r1 = r0 + 8;
    const bool v0 = r0 < 49, v1 = r1 < 49;

    const unsigned xAddr  = su + XS_OFF + (unsigned)((mt * 16 + l15) * RSH + lhi) * 2;
    const unsigned wAddr0 = su + (unsigned)(((nh * 32 + l7) * RSH + l8) * 2);

    // ================ Phase A: QKV projection, 3 tiles (dbl-buffered) ========
    #pragma unroll 1
    for (int wi = 0; wi < 3; wi++) {
        CPA_WAIT(1);
        __syncthreads();          // current tile resident + prior writes visible

        const unsigned wb = wAddr0 + ((wi & 1) ? WT1_OFF : WT0_OFF);
        float4 acc[4];
        #pragma unroll
        for (int a = 0; a < 4; a++) acc[a] = make_float4(0.f, 0.f, 0.f, 0.f);

        #pragma unroll
        for (int kss = 0; kss < 8; kss++) {
            unsigned a0, a1, a2, a3, b0, b1;
            ldsm4(xAddr + kss * 32, a0, a1, a2, a3);
            #pragma unroll
            for (int n4 = 0; n4 < 4; n4++) {
                ldsm2(wb + n4 * 2176 + kss * 32, b0, b1);
                mma16(acc[n4], a0, a1, a2, a3, b0, b1);
            }
        }
        #pragma unroll
        for (int n4 = 0; n4 < 4; n4++) {
            int d  = nh * 32 + n4 * 8 + t2;
            int d3 = wi * 128 + d;
            float bx = __ldg(qkv_b + d3), by = __ldg(qkv_b + d3 + 1);
            if (wi == 0) {
                if (v0) st2(qs + r0 * RSH + d, (acc[n4].x + bx) * SCALE, (acc[n4].y + by) * SCALE);
                if (v1) st2(qs + r1 * RSH + d, (acc[n4].z + bx) * SCALE, (acc[n4].w + by) * SCALE);
            } else if (wi == 1) {
                if (v0) st2(ks + r0 * RSH + d, acc[n4].x + bx, acc[n4].y + by);
                if (v1) st2(ks + r1 * RSH + d, acc[n4].z + bx, acc[n4].w + by);
            } else {
                if (v0) {
                    vt[d * VTS + r0]       = __float2half_rn(acc[n4].x + bx);
                    vt[(d + 1) * VTS + r0] = __float2half_rn(acc[n4].y + by);
                }
                if (v1) {
                    vt[d * VTS + r1]       = __float2half_rn(acc[n4].z + bx);
                    vt[(d + 1) * VTS + r1] = __float2half_rn(acc[n4].w + by);
                }
            }
        }
        __syncthreads();          // all warps done reading this WT buffer

        // kick next async load into the buffer just freed
        if (wi == 0) {            // tile2 -> WT0
            const __half* wsrc = g_qkvw + 2 * 128 * 128;
            #pragma unroll
            for (int it = 0; it < 4; it++) {
                int idx = tid + it * 512, r = idx >> 4, c = idx & 15;
                cpa16(su + WT0_OFF + r * 272 + c * 16, wsrc + r * 128 + c * 8);
            }
            CPA_COMMIT();         // G2
        } else if (wi == 1) {     // proj -> WT1
            #pragma unroll
            for (int it = 0; it < 4; it++) {
                int idx = tid + it * 512, r = idx >> 4, c = idx & 15;
                cpa16(su + WT1_OFF + r * 272 + c * 16, g_projw + r * 128 + c * 8);
            }
            CPA_COMMIT();         // G3
        }
    }
    __syncthreads();              // QS/KS/VT fully visible

    // ================ Phase B: scores + bias -> register softmax -> ATH ======
    {
        const int h = w & 3, mq = w >> 2;
        const int qr0 = mq * 16 + g, qr1 = qr0 + 8;
        const unsigned qAddr = su + QS_OFF + (unsigned)((mq * 16 + l15) * RSH + h * 32 + lhi) * 2;
        const unsigned kAddr = su + KS_OFF + (unsigned)((l7 * RSH + h * 32 + l8) * 2);

        float4 acc[7];
        #pragma unroll
        for (int nt = 0; nt < 7; nt++) acc[nt] = make_float4(0.f, 0.f, 0.f, 0.f);

        #pragma unroll
        for (int kss = 0; kss < 2; kss++) {
            unsigned a0, a1, a2, a3, b0, b1;
            ldsm4(qAddr + kss * 32, a0, a1, a2, a3);
            #pragma unroll
            for (int nt = 0; nt < 7; nt++) {
                ldsm2(kAddr + nt * 2176 + kss * 32, b0, b1);
                mma16(acc[nt], a0, a1, a2, a3, b0, b1);
            }
        }
        // add combined bias, softmax in registers (quad shfl)
        const __half* cb0 = cb + (h * 49 + min(qr0, 48)) * 56;
        const __half* cb1 = cb + (h * 49 + min(qr1, 48)) * 56;
        float m0 = -3.0e38f, m1 = -3.0e38f;
        #pragma unroll
        for (int nt = 0; nt < 7; nt++) {
            int j0 = nt * 8 + t2;
            float2 c0 = __half22float2(*reinterpret_cast<const __half2*>(cb0 + j0));
            float2 c1 = __half22float2(*reinterpret_cast<const __half2*>(cb1 + j0));
            acc[nt].x += c0.x; acc[nt].y += c0.y;
            acc[nt].z += c1.x; acc[nt].w += c1.y;
            m0 = fmaxf(m0, fmaxf(acc[nt].x, acc[nt].y));
            m1 = fmaxf(m1, fmaxf(acc[nt].z, acc[nt].w));
        }
        m0 = fmaxf(m0, __shfl_xor_sync(0xffffffffu, m0, 1));
        m0 = fmaxf(m0, __shfl_xor_sync(0xffffffffu, m0, 2));
        m1 = fmaxf(m1, __shfl_xor_sync(0xffffffffu, m1, 1));
        m1 = fmaxf(m1, __shfl_xor_sync(0xffffffffu, m1, 2));
        float s0 = 0.f, s1 = 0.f;
        #pragma unroll
        for (int nt = 0; nt < 7; nt++) {
            acc[nt].x = __expf(acc[nt].x - m0); acc[nt].y = __expf(acc[nt].y - m0);
            acc[nt].z = __expf(acc[nt].z - m1); acc[nt].w = __expf(acc[nt].w - m1);
            s0 += acc[nt].x + acc[nt].y;
            s1 += acc[nt].z + acc[nt].w;
        }
        s0 += __shfl_xor_sync(0xffffffffu, s0, 1);
        s0 += __shfl_xor_sync(0xffffffffu, s0, 2);
        s1 += __shfl_xor_sync(0xffffffffu, s1, 1);
        s1 += __shfl_xor_sync(0xffffffffu, s1, 2);
        float i0 = 1.0f / s0, i1 = 1.0f / s1;
        __half* pr0 = ath + (h * 64 + qr0) * ATS;
        __half* pr1 = ath + (h * 64 + qr1) * ATS;
        #pragma unroll
        for (int nt = 0; nt < 7; nt++) {
            int j0 = nt * 8 + t2;
            st2(pr0 + j0, acc[nt].x * i0, acc[nt].y * i0);
            st2(pr1 + j0, acc[nt].z * i1, acc[nt].w * i1);
        }
    }
    __syncthreads();              // ATH visible

    // ================ Phase C: O = P @ V -> half O into XS ===================
    {
        const int h = w & 3, mq = w >> 2;
        const int pr0 = mq * 16 + g, pr1 = pr0 + 8;
        const unsigned aAddr = su + ATH_OFF +
            (unsigned)(((h * 64 + mq * 16 + l15) * ATS + lhi) * 2);
        const unsigned vAddr = su + VT_OFF +
            (unsigned)(((h * 32 + l7) * VTS + l8) * 2);

        float4 acc[4];
        #pragma unroll
        for (int nd = 0; nd < 4; nd++) acc[nd] = make_float4(0.f, 0.f, 0.f, 0.f);

        #pragma unroll
        for (int kss = 0; kss < 4; kss++) {
            unsigned a0, a1, a2, a3, b0, b1;
            ldsm4(aAddr + kss * 32, a0, a1, a2, a3);
            #pragma unroll
            for (int nd = 0; nd < 4; nd++) {
                ldsm2(vAddr + nd * (8 * VTS * 2) + kss * 32, b0, b1);
                mma16(acc[nd], a0, a1, a2, a3, b0, b1);
            }
        }
        #pragma unroll
        for (int nd = 0; nd < 4; nd++) {
            int c0 = h * 32 + nd * 8 + t2;
            if (pr0 < 49) st2(xs + pr0 * RSH + c0, acc[nd].x, acc[nd].y);
            if (pr1 < 49) st2(xs + pr1 * RSH + c0, acc[nd].z, acc[nd].w);
        }
    }
    CPA_WAIT(0);                  // proj weights in WT1
    __syncthreads();              // O visible

    // ================ Phase D: out = O @ Wp^T + b ============================
    {
        float* og = out + (size_t)b * (49 * 128);
        const unsigned wb = wAddr0 + WT1_OFF;
        float4 acc[4];
        #pragma unroll
        for (int a = 0; a < 4; a++) acc[a] = make_float4(0.f, 0.f, 0.f, 0.f);

        #pragma unroll
        for (int kss = 0; kss < 8; kss++) {
            unsigned a0, a1, a2, a3, b0, b1;
            ldsm4(xAddr + kss * 32, a0, a1, a2, a3);
            #pragma unroll
            for (int n4 = 0; n4 < 4; n4++) {
                ldsm2(wb + n4 * 2176 + kss * 32, b0, b1);
                mma16(acc[n4], a0, a1, a2, a3, b0, b1);
            }
        }
        #pragma unroll
        for (int n4 = 0; n4 < 4; n4++) {
            int d = nh * 32 + n4 * 8 + t2;
            float bx = __ldg(proj_b + d), by = __ldg(proj_b + d + 1);
            if (v0) {
                og[r0 * 128 + d]     = acc[n4].x + bx;
                og[r0 * 128 + d + 1] = acc[n4].y + by;
            }
            if (v1) {
                og[r1 * 128 + d]     = acc[n4].z + bx;
                og[r1 * 128 + d + 1] = acc[n4].w + by;
            }
        }
    }
}

extern "C" void kernel_launch(void* const* d_in, const int* in_sizes, int n_in,
                              void* d_out, int out_size)
{
    const float* x      = (const float*)d_in[0];
    const float* mask   = (const float*)d_in[1];
    const float* qkv_w  = (const float*)d_in[2];
    const float* qkv_b  = (const float*)d_in[3];
    const float* proj_w = (const float*)d_in[4];
    const float* proj_b = (const float*)d_in[5];
    const float* rpb    = (const float*)d_in[6];
    const int*   rpi    = (const int*)d_in[7];
    float* out = (float*)d_out;

    precompute_k<<<260, 256>>>(mask, qkv_w, proj_w, rpb, rpi);

    cudaFuncSetAttribute(winattn_h2,
                         cudaFuncAttributeMaxDynamicSharedMemorySize,
                         SMEM_BYTES);
    winattn_h2<<<16384, 512, SMEM_BYTES>>>(x, qkv_b, proj_b, out);
}

// round 14
// speedup vs baseline: 12.5222x; 1.2071x over previous
#include <cuda_runtime.h>
#include <cuda_fp16.h>

// WindowAttention fused, fp16 mma.sync + ldmatrix + cp.async.
// R11: register-resident P (no ATH), CB from global, single weight buffer,
// smem 103296 B -> 2 CTAs/SM, __launch_bounds__(512, 2).
// One CTA per window (16384), 512 threads (16 warps).
//
// SMEM:
//  XS  half[64][136]   x, later O            @ 0      (17408)
//  QS  half[64][136]   q*scale               @ 17408  (17408)
//  KS  half[56][136]   k (pad rows zeroed)   @ 34816  (15232)
//  VT  half[128][72]   V^T [dim][tok], zeroed@ 50048  (18432)
//  WT  half[128][136]  weight tile (single)  @ 68480  (34816)
// total 103296 B.

#define XS_OFF   0
#define QS_OFF   17408
#define KS_OFF   34816
#define VT_OFF   50048
#define WT_OFF   68480
#define SMEM_BYTES 103296
#define RSH 136
#define VTS 72
// KS pad rows (49..55) @ 48144, contiguous with VT -> one zero region.
#define ZERO_OFF 48144
#define ZERO_U4  1271   // (1904 + 18432) / 16

__device__ __half g_qkvw[384 * 128];
__device__ __half g_projw[128 * 128];
__device__ __half g_cbias[256 * 4 * 49 * 56];   // [wg][h][i][j-padded]

// ---------------- precompute: half weights + combined bias ------------------
__global__ void precompute_k(const float* __restrict__ mask,
                             const float* __restrict__ qkv_w,
                             const float* __restrict__ proj_w,
                             const float* __restrict__ rpb,
                             const int*   __restrict__ rpi)
{
    int blk = blockIdx.x, tid = threadIdx.x;
    if (blk < 256) {
        const float* mg = mask + (size_t)blk * 2401;
        __half* dst = g_cbias + (size_t)blk * 10976;
        for (int idx = tid; idx < 10976; idx += 256) {
            int h = idx / 2744, rem = idx - h * 2744;
            int i = rem / 56, j = rem - i * 56;
            float v = (j < 49) ? rpb[rpi[i * 49 + j] * 4 + h] + mg[i * 49 + j]
                               : -20000.0f;
            dst[idx] = __float2half_rn(v);
        }
    } else if (blk < 259) {
        int base = (blk - 256) * 16384;
        for (int idx = tid; idx < 16384; idx += 256)
            g_qkvw[base + idx] = __float2half_rn(qkv_w[base + idx]);
    } else {
        for (int idx = tid; idx < 16384; idx += 256)
            g_projw[idx] = __float2half_rn(proj_w[idx]);
    }
}

// ---------------- helpers ---------------------------------------------------
__device__ __forceinline__ void cpa16(unsigned dst, const void* src) {
    asm volatile("cp.async.cg.shared.global [%0], [%1], 16;" :: "r"(dst), "l"(src));
}
#define CPA_COMMIT() asm volatile("cp.async.commit_group;")
#define CPA_WAIT0()  asm volatile("cp.async.wait_group 0;")

__device__ __forceinline__ void ldsm4(unsigned addr, unsigned& r0, unsigned& r1,
                                      unsigned& r2, unsigned& r3) {
    asm volatile("ldmatrix.sync.aligned.m8n8.x4.shared.b16 {%0,%1,%2,%3}, [%4];"
                 : "=r"(r0), "=r"(r1), "=r"(r2), "=r"(r3) : "r"(addr));
}
__device__ __forceinline__ void ldsm2(unsigned addr, unsigned& r0, unsigned& r1) {
    asm volatile("ldmatrix.sync.aligned.m8n8.x2.shared.b16 {%0,%1}, [%2];"
                 : "=r"(r0), "=r"(r1) : "r"(addr));
}
__device__ __forceinline__ void mma16(float4& c, unsigned a0, unsigned a1, unsigned a2,
                                      unsigned a3, unsigned b0, unsigned b1) {
    asm volatile(
        "mma.sync.aligned.m16n8k16.row.col.f32.f16.f16.f32 "
        "{%0,%1,%2,%3},{%4,%5,%6,%7},{%8,%9},{%0,%1,%2,%3};"
        : "+f"(c.x), "+f"(c.y), "+f"(c.z), "+f"(c.w)
        : "r"(a0), "r"(a1), "r"(a2), "r"(a3), "r"(b0), "r"(b1));
}
__device__ __forceinline__ void st2(__half* p, float a, float b) {
    *reinterpret_cast<__half2*>(p) = __floats2half2_rn(a, b);
}
__device__ __forceinline__ unsigned pk(float a, float b) {
    __half2 h = __floats2half2_rn(a, b);
    return *reinterpret_cast<unsigned*>(&h);
}

// ---------------- main kernel ----------------------------------------------
__global__ __launch_bounds__(512, 2)
void winattn_h3(const float* __restrict__ x,
                const float* __restrict__ qkv_b,
                const float* __restrict__ proj_b,
                float* __restrict__ out)
{
    extern __shared__ __align__(16) char smb[];
    __half* xs  = reinterpret_cast<__half*>(smb + XS_OFF);
    __half* qs  = reinterpret_cast<__half*>(smb + QS_OFF);
    __half* ks  = reinterpret_cast<__half*>(smb + KS_OFF);
    __half* vt  = reinterpret_cast<__half*>(smb + VT_OFF);

    const unsigned su = (unsigned)__cvta_generic_to_shared(smb);

    const int b   = blockIdx.x;
    const int tid = threadIdx.x;
    const int w   = tid >> 5;
    const int l   = tid & 31;
    const int g   = l >> 2;
    const int t   = l & 3;
    const int t2  = 2 * t;
    const int l15 = l & 15, lhi = (l >> 4) << 3, l7 = l & 7, l8 = l & 8;

    const float SCALE = 0.17677669529663687f;   // 32^-0.5

    // -- cp.async weight tile 0 first (max overlap with init) --
    #pragma unroll
    for (int it = 0; it < 4; it++) {
        int idx = tid + it * 512, r = idx >> 4, c = idx & 15;
        cpa16(su + WT_OFF + r * 272 + c * 16, g_qkvw + r * 128 + c * 8);
    }
    CPA_COMMIT();

    // -- x -> XS (half); zero KS pad rows + VT (contiguous) --
    {
        const float4* xg = reinterpret_cast<const float4*>(x + (size_t)b * (49 * 128));
        #pragma unroll
        for (int it = 0; it < 4; it++) {
            int idx = tid + it * 512;
            if (idx < 49 * 32) {
                int r = idx >> 5, c = idx & 31;
                float4 v = xg[idx];
                __half* p = xs + r * RSH + c * 4;
                *reinterpret_cast<__half2*>(p)     = __floats2half2_rn(v.x, v.y);
                *reinterpret_cast<__half2*>(p + 2) = __floats2half2_rn(v.z, v.w);
            }
        }
        uint4 z = make_uint4(0, 0, 0, 0);
        uint4* zp = reinterpret_cast<uint4*>(smb + ZERO_OFF);
        #pragma unroll
        for (int it = 0; it < 3; it++) {
            int idx = tid + it * 512;
            if (idx < ZERO_U4) zp[idx] = z;
        }
    }

    const int mt = w & 3, nh = w >> 2;
    const int r0 = mt * 16 + g, r1 = r0 + 8;
    const bool v0 = r0 < 49, v1 = r1 < 49;

    const unsigned xAddr = su + XS_OFF + (unsigned)((mt * 16 + l15) * RSH + lhi) * 2;
    const unsigned wAddr = su + WT_OFF + (unsigned)(((nh * 32 + l7) * RSH + l8) * 2);

    // ================ Phase A: QKV projection, 3 tiles (single buffer) ========
    #pragma unroll 1
    for (int wi = 0; wi < 3; wi++) {
        CPA_WAIT0();
        __syncthreads();          // tile resident + all prior smem writes visible

        float4 acc[4];
        #pragma unroll
        for (int a = 0; a < 4; a++) acc[a] = make_float4(0.f, 0.f, 0.f, 0.f);

        #pragma unroll
        for (int kss = 0; kss < 8; kss++) {
            unsigned a0, a1, a2, a3, b0, b1;
            ldsm4(xAddr + kss * 32, a0, a1, a2, a3);
            #pragma unroll
            for (int n4 = 0; n4 < 4; n4++) {
                ldsm2(wAddr + n4 * 2176 + kss * 32, b0, b1);
                mma16(acc[n4], a0, a1, a2, a3, b0, b1);
            }
        }
        #pragma unroll
        for (int n4 = 0; n4 < 4; n4++) {
            int d  = nh * 32 + n4 * 8 + t2;
            int d3 = wi * 128 + d;
            float bx = __ldg(qkv_b + d3), by = __ldg(qkv_b + d3 + 1);
            if (wi == 0) {
                if (v0) st2(qs + r0 * RSH + d, (acc[n4].x + bx) * SCALE, (acc[n4].y + by) * SCALE);
                if (v1) st2(qs + r1 * RSH + d, (acc[n4].z + bx) * SCALE, (acc[n4].w + by) * SCALE);
            } else if (wi == 1) {
                if (v0) st2(ks + r0 * RSH + d, acc[n4].x + bx, acc[n4].y + by);
                if (v1) st2(ks + r1 * RSH + d, acc[n4].z + bx, acc[n4].w + by);
            } else {
                if (v0) {
                    vt[d * VTS + r0]       = __float2half_rn(acc[n4].x + bx);
                    vt[(d + 1) * VTS + r0] = __float2half_rn(acc[n4].y + by);
                }
                if (v1) {
                    vt[d * VTS + r1]       = __float2half_rn(acc[n4].z + bx);
                    vt[(d + 1) * VTS + r1] = __float2half_rn(acc[n4].w + by);
                }
            }
        }
        __syncthreads();          // all warps done reading WT

        // next tile into the freed buffer: qkv tiles 1,2 then proj
        const __half* nsrc = (wi < 2) ? (g_qkvw + (wi + 1) * 16384) : g_projw;
        #pragma unroll
        for (int it = 0; it < 4; it++) {
            int idx = tid + it * 512, r = idx >> 4, c = idx & 15;
            cpa16(su + WT_OFF + r * 272 + c * 16, nsrc + r * 128 + c * 8);
        }
        CPA_COMMIT();
    }
    // after loop: QS/KS/VT visible (post-wi2 sync); proj load in flight over B+C

    // ================ Phase B: scores + bias -> register softmax ==============
    const int h = w & 3, mq = w >> 2;
    const int qr0 = mq * 16 + g, qr1 = qr0 + 8;

    unsigned pa0[4], pa1[4], pa2[4], pa3[4];    // P fragments for Phase C
    {
        const unsigned qAddr = su + QS_OFF + (unsigned)((mq * 16 + l15) * RSH + h * 32 + lhi) * 2;
        const unsigned kAddr = su + KS_OFF + (unsigned)((l7 * RSH + h * 32 + l8) * 2);

        // prefetch combined bias (global, L1/L2-hot) into regs
        const __half2* cb0 = reinterpret_cast<const __half2*>(
            g_cbias + (size_t)(b & 255) * 10976 + (h * 49 + min(qr0, 48)) * 56);
        const __half2* cb1 = reinterpret_cast<const __half2*>(
            g_cbias + (size_t)(b & 255) * 10976 + (h * 49 + min(qr1, 48)) * 56);
        __half2 c0[7], c1[7];
        #pragma unroll
        for (int nt = 0; nt < 7; nt++) { c0[nt] = cb0[nt * 4 + t]; c1[nt] = cb1[nt * 4 + t]; }

        float4 acc[7];
        #pragma unroll
        for (int nt = 0; nt < 7; nt++) acc[nt] = make_float4(0.f, 0.f, 0.f, 0.f);

        #pragma unroll
        for (int kss = 0; kss < 2; kss++) {
            unsigned a0, a1, a2, a3, b0, b1;
            ldsm4(qAddr + kss * 32, a0, a1, a2, a3);
            #pragma unroll
            for (int nt = 0; nt < 7; nt++) {
                ldsm2(kAddr + nt * 2176 + kss * 32, b0, b1);
                mma16(acc[nt], a0, a1, a2, a3, b0, b1);
            }
        }
        float m0 = -3.0e38f, m1 = -3.0e38f;
        #pragma unroll
        for (int nt = 0; nt < 7; nt++) {
            float2 f0 = __half22float2(c0[nt]);
            float2 f1 = __half22float2(c1[nt]);
            acc[nt].x += f0.x; acc[nt].y += f0.y;
            acc[nt].z += f1.x; acc[nt].w += f1.y;
            m0 = fmaxf(m0, fmaxf(acc[nt].x, acc[nt].y));
            m1 = fmaxf(m1, fmaxf(acc[nt].z, acc[nt].w));
        }
        m0 = fmaxf(m0, __shfl_xor_sync(0xffffffffu, m0, 1));
        m0 = fmaxf(m0, __shfl_xor_sync(0xffffffffu, m0, 2));
        m1 = fmaxf(m1, __shfl_xor_sync(0xffffffffu, m1, 1));
        m1 = fmaxf(m1, __shfl_xor_sync(0xffffffffu, m1, 2));
        float s0 = 0.f, s1 = 0.f;
        #pragma unroll
        for (int nt = 0; nt < 7; nt++) {
            acc[nt].x = __expf(acc[nt].x - m0); acc[nt].y = __expf(acc[nt].y - m0);
            acc[nt].z = __expf(acc[nt].z - m1); acc[nt].w = __expf(acc[nt].w - m1);
            s0 += acc[nt].x + acc[nt].y;
            s1 += acc[nt].z + acc[nt].w;
        }
        s0 += __shfl_xor_sync(0xffffffffu, s0, 1);
        s0 += __shfl_xor_sync(0xffffffffu, s0, 2);
        s1 += __shfl_xor_sync(0xffffffffu, s1, 1);
        s1 += __shfl_xor_sync(0xffffffffu, s1, 2);
        float i0 = 1.0f / s0, i1 = 1.0f / s1;

        // pack normalized probs directly into Phase-C A-fragments:
        // a0=P[r0, k16+t2..], a1=P[r1, ...], a2=P[r0, k16+8+t2..], a3=P[r1, ...]
        #pragma unroll
        for (int kss = 0; kss < 3; kss++) {
            pa0[kss] = pk(acc[2 * kss].x * i0,     acc[2 * kss].y * i0);
            pa1[kss] = pk(acc[2 * kss].z * i1,     acc[2 * kss].w * i1);
            pa2[kss] = pk(acc[2 * kss + 1].x * i0, acc[2 * kss + 1].y * i0);
            pa3[kss] = pk(acc[2 * kss + 1].z * i1, acc[2 * kss + 1].w * i1);
        }
        pa0[3] = pk(acc[6].x * i0, acc[6].y * i0);   // tokens 48..55
        pa1[3] = pk(acc[6].z * i1, acc[6].w * i1);
        pa2[3] = 0u;                                  // tokens 56..63 = 0
        pa3[3] = 0u;
    }
    // no barrier: P lives in registers; Phase C reads only VT (visible since wi2 sync)

    // ================ Phase C: O = P @ V -> half O into XS ====================
    {
        const unsigned vAddr = su + VT_OFF + (unsigned)(((h * 32 + l7) * VTS + l8) * 2);
        float4 acc[4];
        #pragma unroll
        for (int nd = 0; nd < 4; nd++) acc[nd] = make_float4(0.f, 0.f, 0.f, 0.f);

        #pragma unroll
        for (int kss = 0; kss < 4; kss++) {
            unsigned b0, b1;
            #pragma unroll
            for (int nd = 0; nd < 4; nd++) {
                ldsm2(vAddr + nd * (8 * VTS * 2) + kss * 32, b0, b1);
                mma16(acc[nd], pa0[kss], pa1[kss], pa2[kss], pa3[kss], b0, b1);
            }
        }
        #pragma unroll
        for (int nd = 0; nd < 4; nd++) {
            int c0 = h * 32 + nd * 8 + t2;
            if (qr0 < 49) st2(xs + qr0 * RSH + c0, acc[nd].x, acc[nd].y);
            if (qr1 < 49) st2(xs + qr1 * RSH + c0, acc[nd].z, acc[nd].w);
        }
    }
    CPA_WAIT0();                  // proj weights resident in WT
    __syncthreads();              // O visible, all warps past WT consumption

    // ================ Phase D: out = O @ Wp^T + b =============================
    {
        float* og = out + (size_t)b * (49 * 128);
        float4 acc[4];
        #pragma unroll
        for (int a = 0; a < 4; a++) acc[a] = make_float4(0.f, 0.f, 0.f, 0.f);

        #pragma unroll
        for (int kss = 0; kss < 8; kss++) {
            unsigned a0, a1, a2, a3, b0, b1;
            ldsm4(xAddr + kss * 32, a0, a1, a2, a3);
            #pragma unroll
            for (int n4 = 0; n4 < 4; n4++) {
                ldsm2(wAddr + n4 * 2176 + kss * 32, b0, b1);
                mma16(acc[n4], a0, a1, a2, a3, b0, b1);
            }
        }
        #pragma unroll
        for (int n4 = 0; n4 < 4; n4++) {
            int d = nh * 32 + n4 * 8 + t2;
            float bx = __ldg(proj_b + d), by = __ldg(proj_b + d + 1);
            if (v0) {
                og[r0 * 128 + d]     = acc[n4].x + bx;
                og[r0 * 128 + d + 1] = acc[n4].y + by;
            }
            if (v1) {
                og[r1 * 128 + d]     = acc[n4].z + bx;
                og[r1 * 128 + d + 1] = acc[n4].w + by;
            }
        }
    }
}

extern "C" void kernel_launch(void* const* d_in, const int* in_sizes, int n_in,
                              void* d_out, int out_size)
{
    const float* x      = (const float*)d_in[0];
    const float* mask   = (const float*)d_in[1];
    const float* qkv_w  = (const float*)d_in[2];
    const float* qkv_b  = (const float*)d_in[3];
    const float* proj_w = (const float*)d_in[4];
    const float* proj_b = (const float*)d_in[5];
    const float* rpb    = (const float*)d_in[6];
    const int*   rpi    = (const int*)d_in[7];
    float* out = (float*)d_out;

    precompute_k<<<260, 256>>>(mask, qkv_w, proj_w, rpb, rpi);

    cudaFuncSetAttribute(winattn_h3,
                         cudaFuncAttributeMaxDynamicSharedMemorySize,
                         SMEM_BYTES);
    winattn_h3<<<16384, 512, SMEM_BYTES>>>(x, qkv_b, proj_b, out);
}